// round 4
// baseline (speedup 1.0000x reference)
#include <cuda_runtime.h>
#include <cuda_bf16.h>
#include <math.h>
#include <float.h>

// Problem constants
#define B_   2
#define S0_  4096
#define HID_ 1024
#define H_   16
#define D_   64
#define W_   64
#define M_ROWS (B_ * S0_)      // 8192

// Scratch (device globals; allocation is forbidden)
__device__ float g_Q[M_ROWS * HID_];
__device__ float g_K[M_ROWS * HID_];
__device__ float g_V[M_ROWS * HID_];
__device__ float g_CTX[M_ROWS * HID_];

// ---------------------------------------------------------------------------
// SGEMM: C[M,N] = A[M,K] @ B[K,N] + bias[N]
// 128x128 tile, BK=8, 256 threads, 8x8 per-thread register tile.
// M=8192, N=1024, K=1024 (all exact multiples of tile dims).
// ---------------------------------------------------------------------------
__global__ __launch_bounds__(256) void sgemm_bias_kernel(
    const float* __restrict__ A, const float* __restrict__ Bm,
    const float* __restrict__ bias, float* __restrict__ C,
    int M, int N, int K)
{
    constexpr int BM = 128, BN = 128, BK = 8, TM = 8, TN = 8;
    __shared__ float As[BK][BM];
    __shared__ float Bs[BK][BN];

    const int tid = threadIdx.x;
    const int br = blockIdx.y;   // M tile
    const int bc = blockIdx.x;   // N tile
    const int tr = tid / 16;     // 0..15
    const int tc = tid % 16;     // 0..15

    const float* Ab = A + (size_t)br * BM * K;
    const float* Bb = Bm + (size_t)bc * BN;

    float acc[TM][TN];
    #pragma unroll
    for (int i = 0; i < TM; i++)
        #pragma unroll
        for (int j = 0; j < TN; j++) acc[i][j] = 0.0f;

    const int arow = tid / 2;          // 0..127
    const int acol = (tid % 2) * 4;    // 0 or 4
    const int brow = tid / 32;         // 0..7
    const int bcol = (tid % 32) * 4;   // 0..124

    for (int k0 = 0; k0 < K; k0 += BK) {
        float4 a4 = *reinterpret_cast<const float4*>(Ab + (size_t)arow * K + k0 + acol);
        As[acol + 0][arow] = a4.x;
        As[acol + 1][arow] = a4.y;
        As[acol + 2][arow] = a4.z;
        As[acol + 3][arow] = a4.w;

        float4 b4 = *reinterpret_cast<const float4*>(Bb + (size_t)(k0 + brow) * N + bcol);
        *reinterpret_cast<float4*>(&Bs[brow][bcol]) = b4;

        __syncthreads();

        #pragma unroll
        for (int k = 0; k < BK; k++) {
            float ra[TM], rb[TN];
            *reinterpret_cast<float4*>(&ra[0]) = *reinterpret_cast<const float4*>(&As[k][tr * TM]);
            *reinterpret_cast<float4*>(&ra[4]) = *reinterpret_cast<const float4*>(&As[k][tr * TM + 4]);
            *reinterpret_cast<float4*>(&rb[0]) = *reinterpret_cast<const float4*>(&Bs[k][tc * TN]);
            *reinterpret_cast<float4*>(&rb[4]) = *reinterpret_cast<const float4*>(&Bs[k][tc * TN + 4]);
            #pragma unroll
            for (int i = 0; i < TM; i++)
                #pragma unroll
                for (int j = 0; j < TN; j++)
                    acc[i][j] += ra[i] * rb[j];
        }
        __syncthreads();
    }

    #pragma unroll
    for (int i = 0; i < TM; i++) {
        const size_t row = (size_t)br * BM + tr * TM + i;
        #pragma unroll
        for (int j = 0; j < TN; j += 4) {
            const int col = bc * BN + tc * TN + j;
            float4 v;
            v.x = acc[i][j + 0] + bias[col + 0];
            v.y = acc[i][j + 1] + bias[col + 1];
            v.z = acc[i][j + 2] + bias[col + 2];
            v.w = acc[i][j + 3] + bias[col + 3];
            *reinterpret_cast<float4*>(C + row * N + col) = v;
        }
    }
}

// ---------------------------------------------------------------------------
// Sliding-window attention.
// One CTA per (b, h, 64-query tile). Key window = [q0-64, q0+127] (192 keys).
// Query i attends key j iff |i-j| <= 64, j in [0,S0), mask[b,j] > 0.
// 256 threads = 8 warps; each warp processes 8 queries sequentially.
// K/V in smem padded to stride 65 -> conflict-free lane-per-key dot products.
// ---------------------------------------------------------------------------
#define QB 64
#define KW (QB + 2 * W_)       // 192
#define KSTRIDE 65

// dynamic smem layout (floats):
//  Qs   : QB * D_          = 4096
//  Ks   : KW * KSTRIDE     = 12480
//  Vs   : KW * KSTRIDE     = 12480
//  Ps   : 8 * KW           = 1536
//  kval : KW               = 192
#define ATTN_SMEM_FLOATS (QB * D_ + 2 * KW * KSTRIDE + 8 * KW + KW)

__global__ __launch_bounds__(256) void attn_kernel(
    const float* __restrict__ Q, const float* __restrict__ K,
    const float* __restrict__ V, const float* __restrict__ mask,
    float* __restrict__ CTX)
{
    extern __shared__ float sm[];
    float* Qs   = sm;
    float* Ks   = Qs + QB * D_;
    float* Vs   = Ks + KW * KSTRIDE;
    float* Ps   = Vs + KW * KSTRIDE;
    float* kval = Ps + 8 * KW;

    const int bid = blockIdx.x;
    const int qc = bid % (S0_ / QB);
    const int h  = (bid / (S0_ / QB)) % H_;
    const int b  = bid / ((S0_ / QB) * H_);
    const int q0 = qc * QB;
    const int tid = threadIdx.x;

    // Load Q tile: [QB, 64]
    #pragma unroll
    for (int e = tid; e < QB * D_; e += 256) {
        const int qi = e / D_, d = e % D_;
        Qs[qi * D_ + d] = Q[((size_t)(b * S0_ + q0 + qi)) * HID_ + h * D_ + d];
    }
    // Load K/V window with validity
    for (int e = tid; e < KW * D_; e += 256) {
        const int jj = e / D_, d = e % D_;
        const int j = q0 - W_ + jj;
        const bool ok = (j >= 0) && (j < S0_) && (mask[b * S0_ + j] > 0.0f);
        const size_t gidx = ((size_t)(b * S0_ + (ok ? j : 0))) * HID_ + h * D_ + d;
        Ks[jj * KSTRIDE + d] = ok ? K[gidx] : 0.0f;
        Vs[jj * KSTRIDE + d] = ok ? V[gidx] : 0.0f;
        if (d == 0) kval[jj] = ok ? 1.0f : 0.0f;
    }
    __syncthreads();

    const int warpId = tid / 32;
    const int lane = tid % 32;
    float* Pw = Ps + warpId * KW;
    const float scale = 0.125f;   // 1/sqrt(64)

    for (int qi = warpId; qi < QB; qi += 8) {
        // scores: lane handles keys jj = lane + 32*t, t in [0,6)
        float s[6];
        #pragma unroll
        for (int t = 0; t < 6; t++) {
            const int jj = lane + 32 * t;
            float acc = 0.0f;
            const float* kr = Ks + jj * KSTRIDE;
            const float* qr = Qs + qi * D_;
            #pragma unroll
            for (int d = 0; d < D_; d++) acc += qr[d] * kr[d];
            const bool band = (jj >= qi) && (jj <= qi + 2 * W_);
            const bool ok = band && (kval[jj] > 0.0f);
            s[t] = ok ? acc * scale : -FLT_MAX;
        }
        // softmax (warp reduce)
        float m = s[0];
        #pragma unroll
        for (int t = 1; t < 6; t++) m = fmaxf(m, s[t]);
        #pragma unroll
        for (int off = 16; off > 0; off >>= 1)
            m = fmaxf(m, __shfl_xor_sync(0xffffffffu, m, off));
        float sum = 0.0f, e[6];
        #pragma unroll
        for (int t = 0; t < 6; t++) {
            e[t] = (s[t] > -1e30f) ? expf(s[t] - m) : 0.0f;
            sum += e[t];
        }
        #pragma unroll
        for (int off = 16; off > 0; off >>= 1)
            sum += __shfl_xor_sync(0xffffffffu, sum, off);
        const float inv = 1.0f / sum;
        #pragma unroll
        for (int t = 0; t < 6; t++) Pw[lane + 32 * t] = e[t] * inv;
        __syncwarp();

        // output: lane handles dims d = lane, lane+32
        float acc0 = 0.0f, acc1 = 0.0f;
        #pragma unroll 8
        for (int jj = 0; jj < KW; jj++) {
            const float p = Pw[jj];
            acc0 += p * Vs[jj * KSTRIDE + lane];
            acc1 += p * Vs[jj * KSTRIDE + lane + 32];
        }
        float* orow = CTX + ((size_t)(b * S0_ + q0 + qi)) * HID_ + h * D_;
        orow[lane] = acc0;
        orow[lane + 32] = acc1;
        __syncwarp();
    }
}

// ---------------------------------------------------------------------------
extern "C" void kernel_launch(void* const* d_in, const int* in_sizes, int n_in,
                              void* d_out, int out_size)
{
    const float* X    = (const float*)d_in[0];
    const float* mask = (const float*)d_in[1];
    const float* Wq   = (const float*)d_in[2];
    const float* bq   = (const float*)d_in[3];
    const float* Wk   = (const float*)d_in[4];
    const float* bk   = (const float*)d_in[5];
    const float* Wv   = (const float*)d_in[6];
    const float* bv   = (const float*)d_in[7];
    const float* Wo   = (const float*)d_in[8];
    const float* bo   = (const float*)d_in[9];
    float* out = (float*)d_out;

    float *Q, *K, *V, *CTX;
    cudaGetSymbolAddress((void**)&Q, g_Q);
    cudaGetSymbolAddress((void**)&K, g_K);
    cudaGetSymbolAddress((void**)&V, g_V);
    cudaGetSymbolAddress((void**)&CTX, g_CTX);

    dim3 gemm_grid(HID_ / 128, M_ROWS / 128);   // (8, 64)

    sgemm_bias_kernel<<<gemm_grid, 256>>>(X, Wq, bq, Q, M_ROWS, HID_, HID_);
    sgemm_bias_kernel<<<gemm_grid, 256>>>(X, Wk, bk, K, M_ROWS, HID_, HID_);
    sgemm_bias_kernel<<<gemm_grid, 256>>>(X, Wv, bv, V, M_ROWS, HID_, HID_);

    const size_t attn_smem = ATTN_SMEM_FLOATS * sizeof(float);
    cudaFuncSetAttribute(attn_kernel, cudaFuncAttributeMaxDynamicSharedMemorySize,
                         (int)attn_smem);
    const int n_attn_blocks = B_ * H_ * (S0_ / QB);   // 2048
    attn_kernel<<<n_attn_blocks, 256, attn_smem>>>(Q, K, V, mask, CTX);

    sgemm_bias_kernel<<<gemm_grid, 256>>>(CTX, Wo, bo, out, M_ROWS, HID_, HID_);
}

// round 5
// speedup vs baseline: 1.0011x; 1.0011x over previous
#include <cuda_runtime.h>
#include <cuda_bf16.h>
#include <math.h>
#include <float.h>

// Problem constants
#define B_   2
#define S0_  4096
#define HID_ 1024
#define H_   16
#define D_   64
#define W_   64
#define M_ROWS (B_ * S0_)      // 8192

// Scratch (device globals; allocation is forbidden)
__device__ float g_Q[M_ROWS * HID_];
__device__ float g_K[M_ROWS * HID_];
__device__ float g_V[M_ROWS * HID_];
__device__ float g_CTX[M_ROWS * HID_];

// ---------------------------------------------------------------------------
// SGEMM: C[M,N] = A[M,K] @ B[K,N] + bias[N]
// 128x128 tile, BK=8, 256 threads, 8x8 per-thread register tile.
// M=8192, N=1024, K=1024 (all exact multiples of tile dims).
// ---------------------------------------------------------------------------
__global__ __launch_bounds__(256) void sgemm_bias_kernel(
    const float* __restrict__ A, const float* __restrict__ Bm,
    const float* __restrict__ bias, float* __restrict__ C,
    int M, int N, int K)
{
    constexpr int BM = 128, BN = 128, BK = 8, TM = 8, TN = 8;
    __shared__ float As[BK][BM];
    __shared__ float Bs[BK][BN];

    const int tid = threadIdx.x;
    const int br = blockIdx.y;   // M tile
    const int bc = blockIdx.x;   // N tile
    const int tr = tid / 16;     // 0..15
    const int tc = tid % 16;     // 0..15

    const float* Ab = A + (size_t)br * BM * K;
    const float* Bb = Bm + (size_t)bc * BN;

    float acc[TM][TN];
    #pragma unroll
    for (int i = 0; i < TM; i++)
        #pragma unroll
        for (int j = 0; j < TN; j++) acc[i][j] = 0.0f;

    const int arow = tid / 2;          // 0..127
    const int acol = (tid % 2) * 4;    // 0 or 4
    const int brow = tid / 32;         // 0..7
    const int bcol = (tid % 32) * 4;   // 0..124

    for (int k0 = 0; k0 < K; k0 += BK) {
        float4 a4 = *reinterpret_cast<const float4*>(Ab + (size_t)arow * K + k0 + acol);
        As[acol + 0][arow] = a4.x;
        As[acol + 1][arow] = a4.y;
        As[acol + 2][arow] = a4.z;
        As[acol + 3][arow] = a4.w;

        float4 b4 = *reinterpret_cast<const float4*>(Bb + (size_t)(k0 + brow) * N + bcol);
        *reinterpret_cast<float4*>(&Bs[brow][bcol]) = b4;

        __syncthreads();

        #pragma unroll
        for (int k = 0; k < BK; k++) {
            float ra[TM], rb[TN];
            *reinterpret_cast<float4*>(&ra[0]) = *reinterpret_cast<const float4*>(&As[k][tr * TM]);
            *reinterpret_cast<float4*>(&ra[4]) = *reinterpret_cast<const float4*>(&As[k][tr * TM + 4]);
            *reinterpret_cast<float4*>(&rb[0]) = *reinterpret_cast<const float4*>(&Bs[k][tc * TN]);
            *reinterpret_cast<float4*>(&rb[4]) = *reinterpret_cast<const float4*>(&Bs[k][tc * TN + 4]);
            #pragma unroll
            for (int i = 0; i < TM; i++)
                #pragma unroll
                for (int j = 0; j < TN; j++)
                    acc[i][j] += ra[i] * rb[j];
        }
        __syncthreads();
    }

    #pragma unroll
    for (int i = 0; i < TM; i++) {
        const size_t row = (size_t)br * BM + tr * TM + i;
        #pragma unroll
        for (int j = 0; j < TN; j += 4) {
            const int col = bc * BN + tc * TN + j;
            float4 v;
            v.x = acc[i][j + 0] + bias[col + 0];
            v.y = acc[i][j + 1] + bias[col + 1];
            v.z = acc[i][j + 2] + bias[col + 2];
            v.w = acc[i][j + 3] + bias[col + 3];
            *reinterpret_cast<float4*>(C + row * N + col) = v;
        }
    }
}

// ---------------------------------------------------------------------------
// Sliding-window attention.
// One CTA per (b, h, 64-query tile). Key window = [q0-64, q0+127] (192 keys).
// Query i attends key j iff |i-j| <= 64, j in [0,S0), mask[b,j] > 0.
// 256 threads = 8 warps; each warp processes 8 queries sequentially.
// K/V in smem padded to stride 65 -> conflict-free lane-per-key dot products.
// ---------------------------------------------------------------------------
#define QB 64
#define KW (QB + 2 * W_)       // 192
#define KSTRIDE 65

// dynamic smem layout (floats):
//  Qs   : QB * D_          = 4096
//  Ks   : KW * KSTRIDE     = 12480
//  Vs   : KW * KSTRIDE     = 12480
//  Ps   : 8 * KW           = 1536
//  kval : KW               = 192
#define ATTN_SMEM_FLOATS (QB * D_ + 2 * KW * KSTRIDE + 8 * KW + KW)

__global__ __launch_bounds__(256) void attn_kernel(
    const float* __restrict__ Q, const float* __restrict__ K,
    const float* __restrict__ V, const float* __restrict__ mask,
    float* __restrict__ CTX)
{
    extern __shared__ float sm[];
    float* Qs   = sm;
    float* Ks   = Qs + QB * D_;
    float* Vs   = Ks + KW * KSTRIDE;
    float* Ps   = Vs + KW * KSTRIDE;
    float* kval = Ps + 8 * KW;

    const int bid = blockIdx.x;
    const int qc = bid % (S0_ / QB);
    const int h  = (bid / (S0_ / QB)) % H_;
    const int b  = bid / ((S0_ / QB) * H_);
    const int q0 = qc * QB;
    const int tid = threadIdx.x;

    // Load Q tile: [QB, 64]
    #pragma unroll
    for (int e = tid; e < QB * D_; e += 256) {
        const int qi = e / D_, d = e % D_;
        Qs[qi * D_ + d] = Q[((size_t)(b * S0_ + q0 + qi)) * HID_ + h * D_ + d];
    }
    // Load K/V window with validity
    for (int e = tid; e < KW * D_; e += 256) {
        const int jj = e / D_, d = e % D_;
        const int j = q0 - W_ + jj;
        const bool ok = (j >= 0) && (j < S0_) && (mask[b * S0_ + j] > 0.0f);
        const size_t gidx = ((size_t)(b * S0_ + (ok ? j : 0))) * HID_ + h * D_ + d;
        Ks[jj * KSTRIDE + d] = ok ? K[gidx] : 0.0f;
        Vs[jj * KSTRIDE + d] = ok ? V[gidx] : 0.0f;
        if (d == 0) kval[jj] = ok ? 1.0f : 0.0f;
    }
    __syncthreads();

    const int warpId = tid / 32;
    const int lane = tid % 32;
    float* Pw = Ps + warpId * KW;
    const float scale = 0.125f;   // 1/sqrt(64)

    for (int qi = warpId; qi < QB; qi += 8) {
        // scores: lane handles keys jj = lane + 32*t, t in [0,6)
        float s[6];
        #pragma unroll
        for (int t = 0; t < 6; t++) {
            const int jj = lane + 32 * t;
            float acc = 0.0f;
            const float* kr = Ks + jj * KSTRIDE;
            const float* qr = Qs + qi * D_;
            #pragma unroll
            for (int d = 0; d < D_; d++) acc += qr[d] * kr[d];
            const bool band = (jj >= qi) && (jj <= qi + 2 * W_);
            const bool ok = band && (kval[jj] > 0.0f);
            s[t] = ok ? acc * scale : -FLT_MAX;
        }
        // softmax (warp reduce)
        float m = s[0];
        #pragma unroll
        for (int t = 1; t < 6; t++) m = fmaxf(m, s[t]);
        #pragma unroll
        for (int off = 16; off > 0; off >>= 1)
            m = fmaxf(m, __shfl_xor_sync(0xffffffffu, m, off));
        float sum = 0.0f, e[6];
        #pragma unroll
        for (int t = 0; t < 6; t++) {
            e[t] = (s[t] > -1e30f) ? expf(s[t] - m) : 0.0f;
            sum += e[t];
        }
        #pragma unroll
        for (int off = 16; off > 0; off >>= 1)
            sum += __shfl_xor_sync(0xffffffffu, sum, off);
        const float inv = 1.0f / sum;
        #pragma unroll
        for (int t = 0; t < 6; t++) Pw[lane + 32 * t] = e[t] * inv;
        __syncwarp();

        // output: lane handles dims d = lane, lane+32
        float acc0 = 0.0f, acc1 = 0.0f;
        #pragma unroll 8
        for (int jj = 0; jj < KW; jj++) {
            const float p = Pw[jj];
            acc0 += p * Vs[jj * KSTRIDE + lane];
            acc1 += p * Vs[jj * KSTRIDE + lane + 32];
        }
        float* orow = CTX + ((size_t)(b * S0_ + q0 + qi)) * HID_ + h * D_;
        orow[lane] = acc0;
        orow[lane + 32] = acc1;
        __syncwarp();
    }
}

// ---------------------------------------------------------------------------
extern "C" void kernel_launch(void* const* d_in, const int* in_sizes, int n_in,
                              void* d_out, int out_size)
{
    const float* X    = (const float*)d_in[0];
    const float* mask = (const float*)d_in[1];
    const float* Wq   = (const float*)d_in[2];
    const float* bq   = (const float*)d_in[3];
    const float* Wk   = (const float*)d_in[4];
    const float* bk   = (const float*)d_in[5];
    const float* Wv   = (const float*)d_in[6];
    const float* bv   = (const float*)d_in[7];
    const float* Wo   = (const float*)d_in[8];
    const float* bo   = (const float*)d_in[9];
    float* out = (float*)d_out;

    float *Q, *K, *V, *CTX;
    cudaGetSymbolAddress((void**)&Q, g_Q);
    cudaGetSymbolAddress((void**)&K, g_K);
    cudaGetSymbolAddress((void**)&V, g_V);
    cudaGetSymbolAddress((void**)&CTX, g_CTX);

    dim3 gemm_grid(HID_ / 128, M_ROWS / 128);   // (8, 64)

    sgemm_bias_kernel<<<gemm_grid, 256>>>(X, Wq, bq, Q, M_ROWS, HID_, HID_);
    sgemm_bias_kernel<<<gemm_grid, 256>>>(X, Wk, bk, K, M_ROWS, HID_, HID_);
    sgemm_bias_kernel<<<gemm_grid, 256>>>(X, Wv, bv, V, M_ROWS, HID_, HID_);

    const size_t attn_smem = ATTN_SMEM_FLOATS * sizeof(float);
    cudaFuncSetAttribute(attn_kernel, cudaFuncAttributeMaxDynamicSharedMemorySize,
                         (int)attn_smem);
    const int n_attn_blocks = B_ * H_ * (S0_ / QB);   // 2048
    attn_kernel<<<n_attn_blocks, 256, attn_smem>>>(Q, K, V, mask, CTX);

    sgemm_bias_kernel<<<gemm_grid, 256>>>(CTX, Wo, bo, out, M_ROWS, HID_, HID_);
}